// round 1
// baseline (speedup 1.0000x reference)
#include <cuda_runtime.h>

#define NBODY  63
#define NHINGE 61
#define NSITES 16
#define QDIM   68   // 7 free-joint + 61 hinge

// Per-hinge folded constants + site metadata, produced by fk_init each launch.
struct FKConst {
    float4 Q1[NHINGE];        // body_quat[bid]              (w,x,y,z)
    float4 Q2[NHINGE];        // qmul(body_quat[bid],(0,ax)) (w,x,y,z)
    float4 V1[NHINGE];        // body_pos[bid] + jnt_pos[h]
    float4 V2[NHINGE];        // jnt_pos[h]
    float4 SP[NSITES];        // site_pos
    unsigned int mask[NBODY]; // bitmask of sites attached to each body
};
__device__ FKConst g_fk;

__global__ void fk_init(const float* __restrict__ body_pos,
                        const float* __restrict__ body_quat,
                        const float* __restrict__ hinge_axis,
                        const float* __restrict__ jnt_pos,
                        const float* __restrict__ site_pos,
                        const int*   __restrict__ site_body) {
    int t = threadIdx.x;
    if (t < NBODY) g_fk.mask[t] = 0u;
    if (t < NHINGE) {
        int bid = t + 2;
        float w1 = body_quat[bid*4+0], x1 = body_quat[bid*4+1];
        float y1 = body_quat[bid*4+2], z1 = body_quat[bid*4+3];
        float ax = hinge_axis[t*3+0], ay = hinge_axis[t*3+1], az = hinge_axis[t*3+2];
        g_fk.Q1[t] = make_float4(w1, x1, y1, z1);
        // qmul(Q1, (0, ax, ay, az))
        g_fk.Q2[t] = make_float4(-x1*ax - y1*ay - z1*az,
                                  w1*ax + y1*az - z1*ay,
                                  w1*ay - x1*az + z1*ax,
                                  w1*az + x1*ay - y1*ax);
        float jx = jnt_pos[t*3+0], jy = jnt_pos[t*3+1], jz = jnt_pos[t*3+2];
        g_fk.V1[t] = make_float4(body_pos[bid*3+0] + jx,
                                 body_pos[bid*3+1] + jy,
                                 body_pos[bid*3+2] + jz, 0.f);
        g_fk.V2[t] = make_float4(jx, jy, jz, 0.f);
    }
    if (t < NSITES)
        g_fk.SP[t] = make_float4(site_pos[t*3+0], site_pos[t*3+1], site_pos[t*3+2], 0.f);
    __syncthreads();
    if (t < NSITES)
        atomicOr(&g_fk.mask[site_body[t]], 1u << t);
}

__global__ __launch_bounds__(256)
void fk_main(const float* __restrict__ qpos, float* __restrict__ out, int B) {
    __shared__ float4 sQ1[NHINGE], sQ2[NHINGE], sV1[NHINGE], sV2[NHINGE];
    __shared__ float4 sSP[NSITES];
    __shared__ unsigned int sMask[NBODY];

    for (int i = threadIdx.x; i < NHINGE; i += blockDim.x) {
        sQ1[i] = g_fk.Q1[i]; sQ2[i] = g_fk.Q2[i];
        sV1[i] = g_fk.V1[i]; sV2[i] = g_fk.V2[i];
    }
    if (threadIdx.x < NSITES) sSP[threadIdx.x] = g_fk.SP[threadIdx.x];
    if (threadIdx.x < NBODY)  sMask[threadIdx.x] = g_fk.mask[threadIdx.x];
    __syncthreads();

    int b = blockIdx.x * blockDim.x + threadIdx.x;
    if (b >= B) return;

    const float* qp = qpos + (size_t)b * QDIM;
    float* ob = out + (size_t)b * (NSITES * 3);

    // Free joint (body 1)
    float wpx = qp[0], wpy = qp[1], wpz = qp[2];
    float qw = qp[3], qx = qp[4], qy = qp[5], qz = qp[6];
    float rn = rsqrtf(qw*qw + qx*qx + qy*qy + qz*qz);
    qw *= rn; qx *= rn; qy *= rn; qz *= rn;

    // Sites attached to body 1
    unsigned int m1 = sMask[1];
    while (m1) {
        int s = __ffs(m1) - 1; m1 &= m1 - 1;
        float4 sp = sSP[s];
        float tx = 2.f*(qy*sp.z - qz*sp.y);
        float ty = 2.f*(qz*sp.x - qx*sp.z);
        float tz = 2.f*(qx*sp.y - qy*sp.x);
        ob[s*3+0] = wpx + sp.x + qw*tx + (qy*tz - qz*ty);
        ob[s*3+1] = wpy + sp.y + qw*ty + (qz*tx - qx*tz);
        ob[s*3+2] = wpz + sp.z + qw*tz + (qx*ty - qy*tx);
    }

    #pragma unroll 4
    for (int h = 0; h < NHINGE; ++h) {
        float ang = 0.5f * __ldg(qp + 7 + h);
        float sn, cs;
        __sincosf(ang, &sn, &cs);

        // local_combined = cs*Q1 + sn*Q2
        float4 Q1 = sQ1[h], Q2 = sQ2[h];
        float lw = cs*Q1.x + sn*Q2.x;
        float lx = cs*Q1.y + sn*Q2.y;
        float ly = cs*Q1.z + sn*Q2.z;
        float lz = cs*Q1.w + sn*Q2.w;

        // nq = qmul(wq, local)
        float nw = qw*lw - qx*lx - qy*ly - qz*lz;
        float nx = qw*lx + qx*lw + qy*lz - qz*ly;
        float ny = qw*ly - qx*lz + qy*lw + qz*lx;
        float nz = qw*lz + qx*ly - qy*lx + qz*lw;

        // anchor = wp + qrot(wq, V1)
        float4 v1 = sV1[h];
        float tx = 2.f*(qy*v1.z - qz*v1.y);
        float ty = 2.f*(qz*v1.x - qx*v1.z);
        float tz = 2.f*(qx*v1.y - qy*v1.x);
        float anx = wpx + v1.x + qw*tx + (qy*tz - qz*ty);
        float any_ = wpy + v1.y + qw*ty + (qz*tx - qx*tz);
        float anz = wpz + v1.z + qw*tz + (qx*ty - qy*tx);

        // wp = anchor - qrot(nq, V2)
        float4 v2 = sV2[h];
        float sx = 2.f*(ny*v2.z - nz*v2.y);
        float sy = 2.f*(nz*v2.x - nx*v2.z);
        float sz = 2.f*(nx*v2.y - ny*v2.x);
        wpx = anx  - (v2.x + nw*sx + (ny*sz - nz*sy));
        wpy = any_ - (v2.y + nw*sy + (nz*sx - nx*sz));
        wpz = anz  - (v2.z + nw*sz + (nx*sy - ny*sx));

        qw = nw; qx = nx; qy = ny; qz = nz;

        unsigned int mm = sMask[h + 2];
        if (mm) {
            do {
                int s = __ffs(mm) - 1; mm &= mm - 1;
                float4 sp = sSP[s];
                float ux = 2.f*(qy*sp.z - qz*sp.y);
                float uy = 2.f*(qz*sp.x - qx*sp.z);
                float uz = 2.f*(qx*sp.y - qy*sp.x);
                ob[s*3+0] = wpx + sp.x + qw*ux + (qy*uz - qz*uy);
                ob[s*3+1] = wpy + sp.y + qw*uy + (qz*ux - qx*uz);
                ob[s*3+2] = wpz + sp.z + qw*uz + (qx*uy - qy*ux);
            } while (mm);
        }
    }
}

extern "C" void kernel_launch(void* const* d_in, const int* in_sizes, int n_in,
                              void* d_out, int out_size) {
    const float* qpos       = (const float*)d_in[0];
    const float* body_pos   = (const float*)d_in[1];
    const float* body_quat  = (const float*)d_in[2];
    const float* hinge_axis = (const float*)d_in[3];
    const float* jnt_pos    = (const float*)d_in[4];
    const float* site_pos   = (const float*)d_in[5];
    // d_in[6] = body_parent: chain topology (parent = bid-1) is guaranteed by setup
    const int*   site_body  = (const int*)d_in[7];

    int B = in_sizes[0] / QDIM;

    fk_init<<<1, 64>>>(body_pos, body_quat, hinge_axis, jnt_pos, site_pos, site_body);
    fk_main<<<(B + 255) / 256, 256>>>(qpos, (float*)d_out, B);
}

// round 4
// speedup vs baseline: 1.4868x; 1.4868x over previous
#include <cuda_runtime.h>

#define NBODY  63
#define NHINGE 61
#define NSITES 16
#define QDIM   68   // 7 free-joint + 61 hinge
#define BLK    128

// Per-hinge folded constants + site metadata, produced by fk_init each launch.
struct FKConst {
    float4 Q1[NHINGE];        // body_quat[bid]              (w,x,y,z)
    float4 Q2[NHINGE];        // qmul(body_quat[bid],(0,ax)) (w,x,y,z)
    float4 V1[NHINGE];        // body_pos[bid] + jnt_pos[h]
    float4 V2[NHINGE];        // jnt_pos[h]
    float4 SP[NSITES];        // site_pos
    unsigned int mask[NBODY]; // bitmask of sites attached to each body
};
__device__ FKConst g_fk;

__global__ void fk_init(const float* __restrict__ body_pos,
                        const float* __restrict__ body_quat,
                        const float* __restrict__ hinge_axis,
                        const float* __restrict__ jnt_pos,
                        const float* __restrict__ site_pos,
                        const int*   __restrict__ site_body) {
    int t = threadIdx.x;
    if (t < NBODY) g_fk.mask[t] = 0u;
    if (t < NHINGE) {
        int bid = t + 2;
        float w1 = body_quat[bid*4+0], x1 = body_quat[bid*4+1];
        float y1 = body_quat[bid*4+2], z1 = body_quat[bid*4+3];
        float ax = hinge_axis[t*3+0], ay = hinge_axis[t*3+1], az = hinge_axis[t*3+2];
        g_fk.Q1[t] = make_float4(w1, x1, y1, z1);
        g_fk.Q2[t] = make_float4(-x1*ax - y1*ay - z1*az,
                                  w1*ax + y1*az - z1*ay,
                                  w1*ay - x1*az + z1*ax,
                                  w1*az + x1*ay - y1*ax);
        float jx = jnt_pos[t*3+0], jy = jnt_pos[t*3+1], jz = jnt_pos[t*3+2];
        g_fk.V1[t] = make_float4(body_pos[bid*3+0] + jx,
                                 body_pos[bid*3+1] + jy,
                                 body_pos[bid*3+2] + jz, 0.f);
        g_fk.V2[t] = make_float4(jx, jy, jz, 0.f);
    }
    if (t < NSITES)
        g_fk.SP[t] = make_float4(site_pos[t*3+0], site_pos[t*3+1], site_pos[t*3+2], 0.f);
    __syncthreads();
    if (t < NSITES)
        atomicOr(&g_fk.mask[site_body[t]], 1u << t);
}

__global__ __launch_bounds__(BLK, 7)
void fk_main(const float* __restrict__ qpos, float* __restrict__ out, int B) {
    __shared__ float4 sQ1[NHINGE], sQ2[NHINGE], sV1[NHINGE], sV2[NHINGE];
    __shared__ float4 sSP[NSITES];
    __shared__ unsigned int sMask[NBODY];
    __shared__ __align__(16) float sOut[BLK * 48];   // staged outputs, contiguous tile

    for (int i = threadIdx.x; i < NHINGE; i += BLK) {
        sQ1[i] = g_fk.Q1[i]; sQ2[i] = g_fk.Q2[i];
        sV1[i] = g_fk.V1[i]; sV2[i] = g_fk.V2[i];
    }
    if (threadIdx.x < NSITES) sSP[threadIdx.x] = g_fk.SP[threadIdx.x];
    if (threadIdx.x < NBODY)  sMask[threadIdx.x] = g_fk.mask[threadIdx.x];
    __syncthreads();

    const int base  = blockIdx.x * BLK;
    const int tid   = threadIdx.x;
    const int b     = base + tid;
    const int nElem = (B - base < BLK) ? (B - base) : BLK;

    if (tid < nElem) {
        const float4* q4 = (const float4*)(qpos + (size_t)b * QDIM);
        float* so = sOut + tid * 48;

        float4 f0 = q4[0];                 // wp.xyz, quat.w
        float4 f1 = q4[1];                 // quat.xyz, angle[0]
        float wpx = f0.x, wpy = f0.y, wpz = f0.z;
        float qw = f0.w, qx = f1.x, qy = f1.y, qz = f1.z;
        float rn = rsqrtf(qw*qw + qx*qx + qy*qy + qz*qz);
        qw *= rn; qx *= rn; qy *= rn; qz *= rn;

        // Sites attached to body 1
        unsigned int m1 = sMask[1];
        while (m1) {
            int s = __ffs(m1) - 1; m1 &= m1 - 1;
            float4 sp = sSP[s];
            float tx = 2.f*(qy*sp.z - qz*sp.y);
            float ty = 2.f*(qz*sp.x - qx*sp.z);
            float tz = 2.f*(qx*sp.y - qy*sp.x);
            so[s*3+0] = wpx + sp.x + qw*tx + (qy*tz - qz*ty);
            so[s*3+1] = wpy + sp.y + qw*ty + (qz*tx - qx*tz);
            so[s*3+2] = wpz + sp.z + qw*tz + (qx*ty - qy*tx);
        }

        auto process = [&](int h, float ang) {
            float sn, cs;
            __sincosf(0.5f * ang, &sn, &cs);

            float4 Q1 = sQ1[h], Q2 = sQ2[h];
            float lw = cs*Q1.x + sn*Q2.x;
            float lx = cs*Q1.y + sn*Q2.y;
            float ly = cs*Q1.z + sn*Q2.z;
            float lz = cs*Q1.w + sn*Q2.w;

            float nw = qw*lw - qx*lx - qy*ly - qz*lz;
            float nx = qw*lx + qx*lw + qy*lz - qz*ly;
            float ny = qw*ly - qx*lz + qy*lw + qz*lx;
            float nz = qw*lz + qx*ly - qy*lx + qz*lw;

            float4 v1 = sV1[h];
            float tx = 2.f*(qy*v1.z - qz*v1.y);
            float ty = 2.f*(qz*v1.x - qx*v1.z);
            float tz = 2.f*(qx*v1.y - qy*v1.x);
            float anx = wpx + v1.x + qw*tx + (qy*tz - qz*ty);
            float any_ = wpy + v1.y + qw*ty + (qz*tx - qx*tz);
            float anz = wpz + v1.z + qw*tz + (qx*ty - qy*tx);

            float4 v2 = sV2[h];
            float sx = 2.f*(ny*v2.z - nz*v2.y);
            float sy = 2.f*(nz*v2.x - nx*v2.z);
            float sz = 2.f*(nx*v2.y - ny*v2.x);
            wpx = anx  - (v2.x + nw*sx + (ny*sz - nz*sy));
            wpy = any_ - (v2.y + nw*sy + (nz*sx - nx*sz));
            wpz = anz  - (v2.z + nw*sz + (nx*sy - ny*sx));

            qw = nw; qx = nx; qy = ny; qz = nz;

            unsigned int mm = sMask[h + 2];
            while (mm) {
                int s = __ffs(mm) - 1; mm &= mm - 1;
                float4 sp = sSP[s];
                float ux = 2.f*(qy*sp.z - qz*sp.y);
                float uy = 2.f*(qz*sp.x - qx*sp.z);
                float uz = 2.f*(qx*sp.y - qy*sp.x);
                so[s*3+0] = wpx + sp.x + qw*ux + (qy*uz - qz*uy);
                so[s*3+1] = wpy + sp.y + qw*uy + (qz*ux - qx*uz);
                so[s*3+2] = wpz + sp.z + qw*uz + (qx*uy - qy*ux);
            }
        };

        // h = 0 from f1.w, then 15 groups of 4 angles via aligned float4 loads
        float4 av = q4[2];
        process(0, f1.w);
        #pragma unroll 1
        for (int g = 0; g < 15; ++g) {
            float4 cur = av;
            if (g < 14) av = q4[3 + g];
            process(4*g + 1, cur.x);
            process(4*g + 2, cur.y);
            process(4*g + 3, cur.z);
            process(4*g + 4, cur.w);
        }
    }

    __syncthreads();

    // Cooperative coalesced store of the contiguous [nElem x 48] float tile
    {
        const float4* sv = (const float4*)sOut;
        float4* ov = (float4*)(out + (size_t)base * 48);
        int total = nElem * 12;   // 48 floats = 12 float4 per element
        for (int i = tid; i < total; i += BLK)
            ov[i] = sv[i];
    }
}

extern "C" void kernel_launch(void* const* d_in, const int* in_sizes, int n_in,
                              void* d_out, int out_size) {
    const float* qpos       = (const float*)d_in[0];
    const float* body_pos   = (const float*)d_in[1];
    const float* body_quat  = (const float*)d_in[2];
    const float* hinge_axis = (const float*)d_in[3];
    const float* jnt_pos    = (const float*)d_in[4];
    const float* site_pos   = (const float*)d_in[5];
    const int*   site_body  = (const int*)d_in[7];

    int B = in_sizes[0] / QDIM;

    static int carveout_set = 0;
    if (!carveout_set) {
        cudaFuncSetAttribute(fk_main, cudaFuncAttributePreferredSharedMemoryCarveout, 100);
        carveout_set = 1;
    }

    fk_init<<<1, 64>>>(body_pos, body_quat, hinge_axis, jnt_pos, site_pos, site_body);
    fk_main<<<(B + BLK - 1) / BLK, BLK>>>(qpos, (float*)d_out, B);
}